// round 2
// baseline (speedup 1.0000x reference)
#include <cuda_runtime.h>

// RuleConstraintLoss — single fused kernel.
// inputs: states f32 [B,L,D], op_types i32 [B,M], op_before_pos i32 [B,M],
//         op_after_pos i32 [B,M], n_ops i32 [B]
// output: f32[4] = {total, identity_loss, cancel_loss, collapse_loss}
//
// Scratch (__device__ globals) is zero at module load; the finalizing block
// resets it to zero after use, so every launch / graph replay sees zeros.

#define OP_IDENTITY     2
#define OP_CANCEL_START 3
#define OP_CANCEL_END   4
#define OP_STAR_ZERO    5
#define EPSF 1e-9f

// slot 0: identity, slot 1: cancel, slot 2: collapse
__device__ double       g_sum[3];
__device__ int          g_cnt[3];
__device__ unsigned int g_ticket;

// 128 threads/block, D = 512 -> each thread owns one float4 of each row.
template<int D>
__global__ void __launch_bounds__(128)
rcl_fused_kernel(const float* __restrict__ states,
                 const int*   __restrict__ op_types,
                 const int*   __restrict__ bp,
                 const int*   __restrict__ ap,
                 const int*   __restrict__ n_ops,
                 int L, int M,
                 float* __restrict__ out) {
    const int gm  = blockIdx.x;
    const int b   = gm / M;
    const int m   = gm - b * M;
    const int tid = threadIdx.x;

    __shared__ float s_red[8];

    // ---------------- per-op work (predicated) ----------------
    const int n   = n_ops[b];
    bool active = (m < n);
    int ot = 0, bpos = 0, apos = 0;
    if (active) {
        const int idx = b * M + m;
        ot   = op_types[idx];
        bpos = bp[idx];
        apos = ap[idx];
        active = (ot == OP_IDENTITY || ot == OP_CANCEL_START || ot == OP_STAR_ZERO)
                 && bpos >= 0 && bpos < L && apos >= 0 && apos < L;
    }

    if (active) {
        const int idx = b * M + m;
        const float4* rowB =
            (const float4*)(states + ((size_t)b * L + (size_t)bpos) * D);

        if (ot == OP_STAR_ZERO) {
            const float4* rowA =
                (const float4*)(states + ((size_t)b * L + (size_t)apos) * D);
            float4 a = rowA[tid];
            float4 c = rowB[tid];
            float ea = a.x*a.x + a.y*a.y + a.z*a.z + a.w*a.w;
            float eb = c.x*c.x + c.y*c.y + c.z*c.z + c.w*c.w;
            #pragma unroll
            for (int o = 16; o > 0; o >>= 1) {
                ea += __shfl_down_sync(0xffffffffu, ea, o);
                eb += __shfl_down_sync(0xffffffffu, eb, o);
            }
            int w = tid >> 5;
            if ((tid & 31) == 0) { s_red[w] = ea; s_red[4 + w] = eb; }
            __syncthreads();
            float Ea = s_red[0] + s_red[1] + s_red[2] + s_red[3];
            float Eb = s_red[4] + s_red[5] + s_red[6] + s_red[7];
            float invA = 1.0f / (Ea + EPSF);
            float invB = 1.0f / (Eb + EPSF);
            float ha = 0.f, hb = 0.f;
            {
                float e, p;
                e = a.x*a.x; p = e*invA; ha -= p * __log2f(p + EPSF);
                e = a.y*a.y; p = e*invA; ha -= p * __log2f(p + EPSF);
                e = a.z*a.z; p = e*invA; ha -= p * __log2f(p + EPSF);
                e = a.w*a.w; p = e*invA; ha -= p * __log2f(p + EPSF);
                e = c.x*c.x; p = e*invB; hb -= p * __log2f(p + EPSF);
                e = c.y*c.y; p = e*invB; hb -= p * __log2f(p + EPSF);
                e = c.z*c.z; p = e*invB; hb -= p * __log2f(p + EPSF);
                e = c.w*c.w; p = e*invB; hb -= p * __log2f(p + EPSF);
            }
            __syncthreads();
            #pragma unroll
            for (int o = 16; o > 0; o >>= 1) {
                ha += __shfl_down_sync(0xffffffffu, ha, o);
                hb += __shfl_down_sync(0xffffffffu, hb, o);
            }
            if ((tid & 31) == 0) { s_red[w] = ha; s_red[4 + w] = hb; }
            __syncthreads();
            if (tid == 0) {
                float enta = s_red[0] + s_red[1] + s_red[2] + s_red[3];
                float entb = s_red[4] + s_red[5] + s_red[6] + s_red[7];
                float term = enta - entb + 0.5f;
                term = term > 0.f ? term : 0.f;
                atomicAdd(&g_sum[2], (double)term);
                atomicAdd(&g_cnt[2], 1);
            }
        } else {
            // identity or cancel-start
            int tpos = apos;
            int slot = 0;
            bool ok = true;
            if (ot == OP_CANCEL_START) {
                slot = 1;
                if (m + 1 >= n || m + 1 >= M) {
                    ok = false;
                } else {
                    int otn = op_types[idx + 1];
                    int apn = ap[idx + 1];
                    if (otn != OP_CANCEL_END || apn < 0 || apn >= L) ok = false;
                    else tpos = apn;
                }
            }
            if (ok) {
                const float4* rowA =
                    (const float4*)(states + ((size_t)b * L + (size_t)tpos) * D);
                float4 a = rowA[tid];
                float4 c = rowB[tid];
                float d0 = a.x - c.x, d1 = a.y - c.y, d2 = a.z - c.z, d3 = a.w - c.w;
                float s = d0*d0 + d1*d1 + d2*d2 + d3*d3;
                #pragma unroll
                for (int o = 16; o > 0; o >>= 1)
                    s += __shfl_down_sync(0xffffffffu, s, o);
                int w = tid >> 5;
                if ((tid & 31) == 0) s_red[w] = s;
                __syncthreads();
                if (tid == 0) {
                    float tot = (s_red[0] + s_red[1] + s_red[2] + s_red[3])
                                * (1.0f / (float)D);
                    atomicAdd(&g_sum[slot], (double)tot);
                    atomicAdd(&g_cnt[slot], 1);
                }
            }
        }
    }

    // ---------------- last-block finalize ----------------
    __syncthreads();           // all contributions from this block issued
    __shared__ unsigned int s_ticket;
    if (tid == 0) {
        __threadfence();       // publish this block's atomics
        s_ticket = atomicAdd(&g_ticket, 1u);
    }
    __syncthreads();
    if (s_ticket == (unsigned int)(gridDim.x - 1)) {
        if (tid == 0) {
            __threadfence();   // acquire all blocks' contributions
            int c0 = g_cnt[0] > 0 ? g_cnt[0] : 1;
            int c1 = g_cnt[1] > 0 ? g_cnt[1] : 1;
            int c2 = g_cnt[2] > 0 ? g_cnt[2] : 1;
            float id = (float)(g_sum[0] / (double)c0);
            float ca = (float)(g_sum[1] / (double)c1);
            float co = (float)(g_sum[2] / (double)c2);
            out[0] = 1.0f * id + 1.0f * ca + 0.5f * co;
            out[1] = id;
            out[2] = ca;
            out[3] = co;
            // reset scratch for the next launch / graph replay
            g_sum[0] = 0.0; g_sum[1] = 0.0; g_sum[2] = 0.0;
            g_cnt[0] = 0;   g_cnt[1] = 0;   g_cnt[2] = 0;
            __threadfence();
            g_ticket = 0u;
        }
    }
}

extern "C" void kernel_launch(void* const* d_in, const int* in_sizes, int n_in,
                              void* d_out, int out_size) {
    const float* states   = (const float*)d_in[0];
    const int*   op_types = (const int*)d_in[1];
    const int*   bp       = (const int*)d_in[2];
    const int*   ap       = (const int*)d_in[3];
    const int*   n_ops    = (const int*)d_in[4];

    const int B = in_sizes[4];
    const int M = in_sizes[1] / B;
    const int D = 512;
    const int L = in_sizes[0] / (B * D);

    rcl_fused_kernel<512><<<B * M, 128>>>(states, op_types, bp, ap, n_ops,
                                          L, M, (float*)d_out);
}

// round 3
// speedup vs baseline: 1.0172x; 1.0172x over previous
#include <cuda_runtime.h>

// RuleConstraintLoss — single persistent fused kernel, warp-per-op.
// inputs: states f32 [B,L,D], op_types i32 [B,M], op_before_pos i32 [B,M],
//         op_after_pos i32 [B,M], n_ops i32 [B]
// output: f32[4] = {total, identity_loss, cancel_loss, collapse_loss}

#define OP_IDENTITY     2
#define OP_CANCEL_START 3
#define OP_CANCEL_END   4
#define OP_STAR_ZERO    5
#define EPSF 1e-9f

#define NBLOCKS 148
#define NTHREADS 256           // 8 warps
#define WARPS_PER_BLOCK (NTHREADS / 32)

// slot 0: identity, slot 1: cancel, slot 2: collapse
__device__ double       g_sum[3];
__device__ int          g_cnt[3];
__device__ unsigned int g_ticket;

__device__ __forceinline__ float warp_sum(float v) {
    #pragma unroll
    for (int o = 16; o > 0; o >>= 1)
        v += __shfl_xor_sync(0xffffffffu, v, o);
    return v;
}

// D = 512: each lane owns 4 float4 (16 floats) of a row.
template<int D>
__global__ void __launch_bounds__(NTHREADS)
rcl_kernel(const float* __restrict__ states,
           const int*   __restrict__ op_types,
           const int*   __restrict__ bp,
           const int*   __restrict__ ap,
           const int*   __restrict__ n_ops,
           int L, int M, int total_ops,
           float* __restrict__ out) {
    const int lane = threadIdx.x & 31;
    const int wid  = threadIdx.x >> 5;

    __shared__ double s_sum[3];
    __shared__ int    s_cnt[3];
    if (threadIdx.x < 3) { s_sum[threadIdx.x] = 0.0; s_cnt[threadIdx.x] = 0; }
    __syncthreads();

    const int warp_global = blockIdx.x * WARPS_PER_BLOCK + wid;
    const int warp_stride = gridDim.x * WARPS_PER_BLOCK;

    for (int op = warp_global; op < total_ops; op += warp_stride) {
        const int b = op / M;
        const int m = op - b * M;

        const int n = n_ops[b];
        if (m >= n) continue;

        const int ot = op_types[op];
        if (ot != OP_IDENTITY && ot != OP_CANCEL_START && ot != OP_STAR_ZERO)
            continue;

        const int bpos = bp[op];
        const int apos = ap[op];
        if (bpos < 0 || bpos >= L || apos < 0 || apos >= L) continue;

        // resolve target row for mse ops
        int tpos = apos;
        int slot = 0;
        if (ot == OP_CANCEL_START) {
            if (m + 1 >= n) continue;
            const int otn = op_types[op + 1];
            const int apn = ap[op + 1];
            if (otn != OP_CANCEL_END || apn < 0 || apn >= L) continue;
            tpos = apn;
            slot = 1;
        }

        const float4* rowB =
            (const float4*)(states + ((size_t)b * L + (size_t)bpos) * D);

        if (ot == OP_STAR_ZERO) {
            const float4* rowA =
                (const float4*)(states + ((size_t)b * L + (size_t)apos) * D);
            float4 a[4], c[4];
            #pragma unroll
            for (int i = 0; i < 4; i++) a[i] = rowA[lane + 32 * i];
            #pragma unroll
            for (int i = 0; i < 4; i++) c[i] = rowB[lane + 32 * i];

            float ea = 0.f, eb = 0.f;
            #pragma unroll
            for (int i = 0; i < 4; i++) {
                ea += a[i].x*a[i].x + a[i].y*a[i].y + a[i].z*a[i].z + a[i].w*a[i].w;
                eb += c[i].x*c[i].x + c[i].y*c[i].y + c[i].z*c[i].z + c[i].w*c[i].w;
            }
            ea = warp_sum(ea);
            eb = warp_sum(eb);
            const float invA = 1.0f / (ea + EPSF);
            const float invB = 1.0f / (eb + EPSF);

            float ha = 0.f, hb = 0.f;
            #pragma unroll
            for (int i = 0; i < 4; i++) {
                float e, p;
                e = a[i].x*a[i].x; p = e*invA; ha -= p * __log2f(p + EPSF);
                e = a[i].y*a[i].y; p = e*invA; ha -= p * __log2f(p + EPSF);
                e = a[i].z*a[i].z; p = e*invA; ha -= p * __log2f(p + EPSF);
                e = a[i].w*a[i].w; p = e*invA; ha -= p * __log2f(p + EPSF);
                e = c[i].x*c[i].x; p = e*invB; hb -= p * __log2f(p + EPSF);
                e = c[i].y*c[i].y; p = e*invB; hb -= p * __log2f(p + EPSF);
                e = c[i].z*c[i].z; p = e*invB; hb -= p * __log2f(p + EPSF);
                e = c[i].w*c[i].w; p = e*invB; hb -= p * __log2f(p + EPSF);
            }
            float diff = warp_sum(ha - hb);
            if (lane == 0) {
                float term = diff + 0.5f;
                term = term > 0.f ? term : 0.f;
                atomicAdd(&s_sum[2], (double)term);
                atomicAdd(&s_cnt[2], 1);
            }
        } else {
            const float4* rowA =
                (const float4*)(states + ((size_t)b * L + (size_t)tpos) * D);
            float s = 0.f;
            #pragma unroll
            for (int i = 0; i < 4; i++) {
                float4 a = rowA[lane + 32 * i];
                float4 c = rowB[lane + 32 * i];
                float d0 = a.x - c.x, d1 = a.y - c.y;
                float d2 = a.z - c.z, d3 = a.w - c.w;
                s += d0*d0 + d1*d1 + d2*d2 + d3*d3;
            }
            s = warp_sum(s);
            if (lane == 0) {
                atomicAdd(&s_sum[slot], (double)(s * (1.0f / (float)D)));
                atomicAdd(&s_cnt[slot], 1);
            }
        }
    }

    // ---------------- block flush + last-block finalize ----------------
    __syncthreads();
    if (threadIdx.x == 0) {
        if (s_cnt[0]) { atomicAdd(&g_sum[0], s_sum[0]); atomicAdd(&g_cnt[0], s_cnt[0]); }
        if (s_cnt[1]) { atomicAdd(&g_sum[1], s_sum[1]); atomicAdd(&g_cnt[1], s_cnt[1]); }
        if (s_cnt[2]) { atomicAdd(&g_sum[2], s_sum[2]); atomicAdd(&g_cnt[2], s_cnt[2]); }
        __threadfence();
        unsigned int t = atomicAdd(&g_ticket, 1u);
        if (t == (unsigned int)(gridDim.x - 1)) {
            __threadfence();
            int c0 = g_cnt[0] > 0 ? g_cnt[0] : 1;
            int c1 = g_cnt[1] > 0 ? g_cnt[1] : 1;
            int c2 = g_cnt[2] > 0 ? g_cnt[2] : 1;
            float id = (float)(g_sum[0] / (double)c0);
            float ca = (float)(g_sum[1] / (double)c1);
            float co = (float)(g_sum[2] / (double)c2);
            float4 o;
            o.x = id + ca + 0.5f * co;
            o.y = id; o.z = ca; o.w = co;
            *(float4*)out = o;
            // reset scratch for next launch / graph replay
            g_sum[0] = 0.0; g_sum[1] = 0.0; g_sum[2] = 0.0;
            g_cnt[0] = 0;   g_cnt[1] = 0;   g_cnt[2] = 0;
            __threadfence();
            g_ticket = 0u;
        }
    }
}

extern "C" void kernel_launch(void* const* d_in, const int* in_sizes, int n_in,
                              void* d_out, int out_size) {
    const float* states   = (const float*)d_in[0];
    const int*   op_types = (const int*)d_in[1];
    const int*   bp       = (const int*)d_in[2];
    const int*   ap       = (const int*)d_in[3];
    const int*   n_ops    = (const int*)d_in[4];

    const int B = in_sizes[4];
    const int M = in_sizes[1] / B;
    const int D = 512;
    const int L = in_sizes[0] / (B * D);

    rcl_kernel<512><<<NBLOCKS, NTHREADS>>>(states, op_types, bp, ap, n_ops,
                                           L, M, B * M, (float*)d_out);
}

// round 4
// speedup vs baseline: 1.4090x; 1.3851x over previous
#include <cuda_runtime.h>

// RuleConstraintLoss — single kernel, one warp per candidate op.
// inputs: states f32 [B,L,D], op_types i32 [B,M], op_before_pos i32 [B,M],
//         op_after_pos i32 [B,M], n_ops i32 [B]
// output: f32[4] = {total, identity_loss, cancel_loss, collapse_loss}

#define OP_IDENTITY     2
#define OP_CANCEL_START 3
#define OP_CANCEL_END   4
#define OP_STAR_ZERO    5
#define EPSF 1e-9f

#define NT  512                 // threads per block
#define WPB (NT / 32)           // 16 warps per block

// slot 0: identity, slot 1: cancel, slot 2: collapse
__device__ double       g_sum[3];
__device__ int          g_cnt[3];
__device__ unsigned int g_ticket;

__device__ __forceinline__ float warp_sum(float v) {
    #pragma unroll
    for (int o = 16; o > 0; o >>= 1)
        v += __shfl_xor_sync(0xffffffffu, v, o);
    return v;
}

// D = 512: each lane owns 4 float4 (16 floats) of each row.
template<int D>
__global__ void __launch_bounds__(NT, 4)
rcl_kernel(const float* __restrict__ states,
           const int*   __restrict__ op_types,
           const int*   __restrict__ bp,
           const int*   __restrict__ ap,
           const int*   __restrict__ n_ops,
           int L, int M, int total_ops,
           float* __restrict__ out) {
    const int lane = threadIdx.x & 31;
    const int wid  = threadIdx.x >> 5;
    const int op   = blockIdx.x * WPB + wid;

    __shared__ double s_sum[3];
    __shared__ int    s_cnt[3];
    if (threadIdx.x < 3) { s_sum[threadIdx.x] = 0.0; s_cnt[threadIdx.x] = 0; }
    __syncthreads();

    if (op < total_ops) {
        const int b = op / M;
        const int m = op - b * M;
        const int opn = (op + 1 < total_ops) ? op + 1 : op;

        // --- issue ALL metadata loads in one batch (independent) ---
        const int n    = n_ops[b];
        const int ot   = op_types[op];
        const int bpos = bp[op];
        const int apos = ap[op];
        const int otn  = op_types[opn];
        const int apn  = ap[opn];

        bool valid = (m < n)
                     && bpos >= 0 && bpos < L && apos >= 0 && apos < L
                     && (ot == OP_IDENTITY || ot == OP_CANCEL_START || ot == OP_STAR_ZERO);

        int tpos = apos;
        int slot = 0;
        if (valid && ot == OP_CANCEL_START) {
            slot = 1;
            if (m + 1 >= n || otn != OP_CANCEL_END || apn < 0 || apn >= L)
                valid = false;
            else
                tpos = apn;
        }

        if (valid) {
            const float4* rowB =
                (const float4*)(states + ((size_t)b * L + (size_t)bpos) * D);

            if (ot == OP_STAR_ZERO) {
                const float4* rowA =
                    (const float4*)(states + ((size_t)b * L + (size_t)apos) * D);
                // pass 1: energy sums (rows pulled into L1)
                float ea = 0.f, eb = 0.f;
                #pragma unroll
                for (int i = 0; i < 4; i++) {
                    float4 a = rowA[lane + 32 * i];
                    float4 c = rowB[lane + 32 * i];
                    ea += a.x*a.x + a.y*a.y + a.z*a.z + a.w*a.w;
                    eb += c.x*c.x + c.y*c.y + c.z*c.z + c.w*c.w;
                }
                ea = warp_sum(ea);
                eb = warp_sum(eb);
                const float invA = 1.0f / (ea + EPSF);
                const float invB = 1.0f / (eb + EPSF);
                // pass 2: entropy (reloads hit L1)
                float h = 0.f;   // ha - hb accumulated directly
                #pragma unroll
                for (int i = 0; i < 4; i++) {
                    float4 a = rowA[lane + 32 * i];
                    float4 c = rowB[lane + 32 * i];
                    float e, p;
                    e = a.x*a.x; p = e*invA; h -= p * __log2f(p + EPSF);
                    e = a.y*a.y; p = e*invA; h -= p * __log2f(p + EPSF);
                    e = a.z*a.z; p = e*invA; h -= p * __log2f(p + EPSF);
                    e = a.w*a.w; p = e*invA; h -= p * __log2f(p + EPSF);
                    e = c.x*c.x; p = e*invB; h += p * __log2f(p + EPSF);
                    e = c.y*c.y; p = e*invB; h += p * __log2f(p + EPSF);
                    e = c.z*c.z; p = e*invB; h += p * __log2f(p + EPSF);
                    e = c.w*c.w; p = e*invB; h += p * __log2f(p + EPSF);
                }
                h = warp_sum(h);
                if (lane == 0) {
                    float term = h + 0.5f;
                    term = term > 0.f ? term : 0.f;
                    atomicAdd(&s_sum[2], (double)term);
                    atomicAdd(&s_cnt[2], 1);
                }
            } else {
                const float4* rowA =
                    (const float4*)(states + ((size_t)b * L + (size_t)tpos) * D);
                float s = 0.f;
                #pragma unroll
                for (int i = 0; i < 4; i++) {
                    float4 a = rowA[lane + 32 * i];
                    float4 c = rowB[lane + 32 * i];
                    float d0 = a.x - c.x, d1 = a.y - c.y;
                    float d2 = a.z - c.z, d3 = a.w - c.w;
                    s += d0*d0 + d1*d1 + d2*d2 + d3*d3;
                }
                s = warp_sum(s);
                if (lane == 0) {
                    atomicAdd(&s_sum[slot], (double)(s * (1.0f / (float)D)));
                    atomicAdd(&s_cnt[slot], 1);
                }
            }
        }
    }

    // ---------------- block flush + last-block finalize ----------------
    __syncthreads();
    if (threadIdx.x == 0) {
        if (s_cnt[0]) { atomicAdd(&g_sum[0], s_sum[0]); atomicAdd(&g_cnt[0], s_cnt[0]); }
        if (s_cnt[1]) { atomicAdd(&g_sum[1], s_sum[1]); atomicAdd(&g_cnt[1], s_cnt[1]); }
        if (s_cnt[2]) { atomicAdd(&g_sum[2], s_sum[2]); atomicAdd(&g_cnt[2], s_cnt[2]); }
        __threadfence();
        unsigned int t = atomicAdd(&g_ticket, 1u);
        if (t == (unsigned int)(gridDim.x - 1)) {
            __threadfence();
            int c0 = g_cnt[0] > 0 ? g_cnt[0] : 1;
            int c1 = g_cnt[1] > 0 ? g_cnt[1] : 1;
            int c2 = g_cnt[2] > 0 ? g_cnt[2] : 1;
            float id = (float)(g_sum[0] / (double)c0);
            float ca = (float)(g_sum[1] / (double)c1);
            float co = (float)(g_sum[2] / (double)c2);
            float4 o;
            o.x = id + ca + 0.5f * co;
            o.y = id; o.z = ca; o.w = co;
            *(float4*)out = o;
            // reset scratch for the next launch / graph replay
            g_sum[0] = 0.0; g_sum[1] = 0.0; g_sum[2] = 0.0;
            g_cnt[0] = 0;   g_cnt[1] = 0;   g_cnt[2] = 0;
            __threadfence();
            g_ticket = 0u;
        }
    }
}

extern "C" void kernel_launch(void* const* d_in, const int* in_sizes, int n_in,
                              void* d_out, int out_size) {
    const float* states   = (const float*)d_in[0];
    const int*   op_types = (const int*)d_in[1];
    const int*   bp       = (const int*)d_in[2];
    const int*   ap       = (const int*)d_in[3];
    const int*   n_ops    = (const int*)d_in[4];

    const int B = in_sizes[4];
    const int M = in_sizes[1] / B;
    const int D = 512;
    const int L = in_sizes[0] / (B * D);
    const int total = B * M;
    const int blocks = (total + WPB - 1) / WPB;

    rcl_kernel<512><<<blocks, NT>>>(states, op_types, bp, ap, n_ops,
                                    L, M, total, (float*)d_out);
}